// round 7
// baseline (speedup 1.0000x reference)
#include <cuda_runtime.h>
#include <math.h>

#define TABLE_SIZE 524288
#define NUM_LEVELS 16
#define N_POINTS   1048576
#define TBL_TOTAL  (TABLE_SIZE * NUM_LEVELS)   // 8388608
#define HMASK      (TABLE_SIZE - 1)
#define P2         2654435761u
#define P3         805459861u

#define MORT_BITS  5
#define NBUCK      32768    // 2^(3*MORT_BITS)
#define SCAN_BLOCKS 32      // 32 scan blocks x 1024 elems

// Repack work split across the three sort-phase kernels.
#define HIST_BLOCKS   4096                 // N_POINTS/256
#define SCAT_BLOCKS   4096
#define R1_BLOCKS     12288
#define R2_BLOCKS1024 3072
#define R3_BLOCKS     8192
#define R_OFF2        (R1_BLOCKS * 256)               // 3145728
#define R_OFF3        (R_OFF2 + R2_BLOCKS1024 * 1024) // 6291456

// Static scratch (allocation-guard safe; zero-initialized at load):
__device__ float2 g_tbl[TBL_TOTAL];      // 64 MB feature-interleaved table
__device__ float4 g_xs[N_POINTS];        // 16 MB sorted points (.w = orig idx)
__device__ int    g_hist[NBUCK];
__device__ int    g_cursor[NBUCK];
__device__ int    g_bsum[SCAN_BLOCKS];

struct ScalArr { float s[NUM_LEVELS]; };

__device__ __forceinline__ void repack_one(const float* __restrict__ ht, int i) {
    float a = __ldg(ht + i);
    float b = __ldg(ht + i + TBL_TOTAL);
    g_tbl[i] = make_float2(a, b);
}

// Gather with L1-allocate (coarse levels: real reuse across nearby blocks).
__device__ __forceinline__ float2 ld_alloc(const float2* p) {
    return __ldg(p);
}
// Gather bypassing L1 allocation (fine levels: random, zero L1 reuse;
// avoids fill wavefronts and pollution of coarse-level lines).
__device__ __forceinline__ float2 ld_noalloc(const float2* p) {
    float2 v;
    asm volatile("ld.global.nc.L1::no_allocate.v2.f32 {%0,%1}, [%2];"
                 : "=f"(v.x), "=f"(v.y) : "l"(p));
    return v;
}

// ---------------------------------------------------------------------------
// Morton bucket (5 bits/dim -> 15-bit code)
// ---------------------------------------------------------------------------
__device__ __forceinline__ unsigned mort5(unsigned v) {
    unsigned m = 0;
    #pragma unroll
    for (int b = 0; b < MORT_BITS; ++b) m |= ((v >> b) & 1u) << (3 * b);
    return m;
}

__device__ __forceinline__ unsigned bucket_of(float x, float y, float z) {
    unsigned ix = min(31u, (unsigned)(int)(x * 32.0f));
    unsigned iy = min(31u, (unsigned)(int)(y * 32.0f));
    unsigned iz = min(31u, (unsigned)(int)(z * 32.0f));
    return mort5(ix) | (mort5(iy) << 1) | (mort5(iz) << 2);
}

// ---------------------------------------------------------------------------
// Phase 1: histogram + repack part 1.
// ---------------------------------------------------------------------------
__global__ __launch_bounds__(256) void combo1_kernel(const float* __restrict__ x,
                                                     const float* __restrict__ ht) {
    int b = blockIdx.x;
    if (b < HIST_BLOCKS) {
        int n = b * 256 + threadIdx.x;
        float vx = x[3 * n + 0], vy = x[3 * n + 1], vz = x[3 * n + 2];
        atomicAdd(&g_hist[bucket_of(vx, vy, vz)], 1);
    } else {
        repack_one(ht, (b - HIST_BLOCKS) * 256 + threadIdx.x);
    }
}

// ---------------------------------------------------------------------------
// Phase 2: per-chunk scan (+ zero g_hist for next replay) + repack part 2.
// ---------------------------------------------------------------------------
__global__ __launch_bounds__(1024) void combo2_kernel(const float* __restrict__ ht) {
    int bid = blockIdx.x;
    int t = threadIdx.x;
    if (bid < SCAN_BLOCKS) {
        __shared__ int sh[1024];
        int i = bid * 1024 + t;
        int v = g_hist[i];
        g_hist[i] = 0;                        // reset for next graph replay
        sh[t] = v;
        __syncthreads();
        #pragma unroll
        for (int off = 1; off < 1024; off <<= 1) {
            int u = (t >= off) ? sh[t - off] : 0;
            __syncthreads();
            sh[t] += u;
            __syncthreads();
        }
        g_cursor[i] = sh[t] - v;              // exclusive within chunk
        if (t == 1023) g_bsum[bid] = sh[t];
    } else {
        repack_one(ht, R_OFF2 + (bid - SCAN_BLOCKS) * 1024 + t);
    }
}

// ---------------------------------------------------------------------------
// Phase 3: scatter (with inline top-level scan) + repack part 3.
// ---------------------------------------------------------------------------
__global__ __launch_bounds__(256) void combo3_kernel(const float* __restrict__ x,
                                                     const float* __restrict__ ht) {
    int bid = blockIdx.x;
    if (bid < SCAT_BLOCKS) {
        __shared__ int sh_boff[SCAN_BLOCKS];
        if (threadIdx.x < 32) {
            int v = g_bsum[threadIdx.x];
            int s = v;
            #pragma unroll
            for (int off = 1; off < 32; off <<= 1) {
                int u = __shfl_up_sync(0xFFFFFFFF, s, off);
                if ((int)threadIdx.x >= off) s += u;
            }
            sh_boff[threadIdx.x] = s - v;
        }
        __syncthreads();
        int n = bid * 256 + threadIdx.x;
        float vx = x[3 * n + 0], vy = x[3 * n + 1], vz = x[3 * n + 2];
        unsigned b = bucket_of(vx, vy, vz);
        int pos = sh_boff[b >> 10] + atomicAdd(&g_cursor[b], 1);
        g_xs[pos] = make_float4(vx, vy, vz, __int_as_float(n));
    } else {
        repack_one(ht, R_OFF3 + (bid - SCAT_BLOCKS) * 256 + threadIdx.x);
    }
}

// ---------------------------------------------------------------------------
// Scrambled weight: fracflat[k] = frac( coord[k%3] * scaling[k/3] )
// ---------------------------------------------------------------------------
__device__ __forceinline__ float fracw(float vx, float vy, float vz,
                                       const float* __restrict__ s, int k) {
    int d = k % 3;
    float v = (d == 0) ? vx : ((d == 1) ? vy : vz);
    float t = v * s[k / 3];
    return t - floorf(t);
}

// One level: gathers + scrambled trilinear blend -> 2 floats.
// L is a compile-time constant after unrolling, so the policy branch folds.
__device__ __forceinline__ void enc_level(float vx, float vy, float vz,
                                          const ScalArr& sc, int L,
                                          float& out0, float& out1) {
    float s  = sc.s[L];
    float sx = vx * s, sy = vy * s, sz = vz * s;

    unsigned fx = (unsigned)(int)floorf(sx);
    unsigned cx = (unsigned)(int)ceilf(sx);
    unsigned fy = (unsigned)(int)floorf(sy);
    unsigned cy = (unsigned)(int)ceilf(sy);
    unsigned fz = (unsigned)(int)floorf(sz);
    unsigned cz = (unsigned)(int)ceilf(sz);

    unsigned hyf = fy * P2, hyc = cy * P2;
    unsigned hzf = fz * P3, hzc = cz * P3;

    const float2* __restrict__ tbl = g_tbl + (size_t)L * TABLE_SIZE;
    bool fine = (L >= 4);

    float2 F0, F1, F2, F3, F4, F5, F6, F7;
    if (fine) {
        F0 = ld_noalloc(tbl + ((cx ^ hyc ^ hzc) & HMASK));
        F1 = ld_noalloc(tbl + ((cx ^ hyc ^ hzf) & HMASK));
        F2 = ld_noalloc(tbl + ((cx ^ hyf ^ hzc) & HMASK));
        F3 = ld_noalloc(tbl + ((fx ^ hyc ^ hzc) & HMASK));
        F4 = ld_noalloc(tbl + ((cx ^ hyf ^ hzf) & HMASK));
        F5 = ld_noalloc(tbl + ((fx ^ hyc ^ hzf) & HMASK));
        F6 = ld_noalloc(tbl + ((fx ^ hyf ^ hzc) & HMASK));
        F7 = ld_noalloc(tbl + ((fx ^ hyf ^ hzf) & HMASK));
    } else {
        F0 = ld_alloc(tbl + ((cx ^ hyc ^ hzc) & HMASK));
        F1 = ld_alloc(tbl + ((cx ^ hyc ^ hzf) & HMASK));
        F2 = ld_alloc(tbl + ((cx ^ hyf ^ hzc) & HMASK));
        F3 = ld_alloc(tbl + ((fx ^ hyc ^ hzc) & HMASK));
        F4 = ld_alloc(tbl + ((cx ^ hyf ^ hzf) & HMASK));
        F5 = ld_alloc(tbl + ((fx ^ hyc ^ hzf) & HMASK));
        F6 = ld_alloc(tbl + ((fx ^ hyf ^ hzc) & HMASK));
        F7 = ld_alloc(tbl + ((fx ^ hyf ^ hzf) & HMASK));
    }

    float wx = fracw(vx, vy, vz, sc.s, L);
    float wy = fracw(vx, vy, vz, sc.s, 16 + L);
    float wz = fracw(vx, vy, vz, sc.s, 32 + L);
    float qx = 1.0f - wx, qy = 1.0f - wy, qz = 1.0f - wz;

    {
        float f03 = F0.x * wx + F3.x * qx;
        float f12 = F1.x * wx + F2.x * qx;
        float f56 = F5.x * wx + F6.x * qx;
        float f47 = F4.x * wx + F7.x * qx;
        float a   = f03 * wy + f12 * qy;
        float b   = f47 * wy + f56 * qy;
        out0 = a * wz + b * qz;
    }
    {
        float f03 = F0.y * wx + F3.y * qx;
        float f12 = F1.y * wx + F2.y * qx;
        float f56 = F5.y * wx + F6.y * qx;
        float f47 = F4.y * wx + F7.y * qx;
        float a   = f03 * wy + f12 * qy;
        float b   = f47 * wy + f56 * qy;
        out1 = a * wz + b * qz;
    }
}

// ---------------------------------------------------------------------------
// Main encoding kernel: one thread per (Morton-sorted) point.
// Level pairs, direct float4 stores (round-5 proven store path).
// ---------------------------------------------------------------------------
__global__ __launch_bounds__(256, 5) void hashenc_kernel(
    float* __restrict__ out,
    ScalArr sc)
{
    int n = blockIdx.x * blockDim.x + threadIdx.x;

    float4 p = g_xs[n];
    float vx = p.x, vy = p.y, vz = p.z;
    int orig = __float_as_int(p.w);

    float4* o = (float4*)(out + (size_t)orig * (2 * NUM_LEVELS));

    #pragma unroll
    for (int Lp = 0; Lp < NUM_LEVELS / 2; ++Lp) {
        float4 r;
        enc_level(vx, vy, vz, sc, 2 * Lp + 0, r.x, r.y);
        enc_level(vx, vy, vz, sc, 2 * Lp + 1, r.z, r.w);
        o[Lp] = r;
    }
}

// ---------------------------------------------------------------------------
// Host: replicate numpy's SCALINGS bit-for-bit with double libm.
// ---------------------------------------------------------------------------
static void compute_scalings(ScalArr& a) {
    double growth = exp((log(2048.0) - log(16.0)) / 15.0);
    for (int l = 0; l < NUM_LEVELS; ++l)
        a.s[l] = (float)floor(16.0 * pow(growth, (double)l));
}

extern "C" void kernel_launch(void* const* d_in, const int* in_sizes, int n_in,
                              void* d_out, int out_size) {
    const float* x  = (const float*)d_in[0];
    const float* ht = (const float*)d_in[1];
    float* out = (float*)d_out;

    ScalArr sc;
    compute_scalings(sc);

    combo1_kernel<<<HIST_BLOCKS + R1_BLOCKS, 256>>>(x, ht);
    combo2_kernel<<<SCAN_BLOCKS + R2_BLOCKS1024, 1024>>>(ht);
    combo3_kernel<<<SCAT_BLOCKS + R3_BLOCKS, 256>>>(x, ht);
    hashenc_kernel<<<N_POINTS / 256, 256>>>(out, sc);
}

// round 8
// speedup vs baseline: 1.0314x; 1.0314x over previous
#include <cuda_runtime.h>
#include <math.h>

#define TABLE_SIZE 524288
#define NUM_LEVELS 16
#define N_POINTS   1048576
#define TBL_TOTAL  (TABLE_SIZE * NUM_LEVELS)   // 8388608
#define HMASK      (TABLE_SIZE - 1)
#define P2         2654435761u
#define P3         805459861u

#define MORT_BITS  5
#define NBUCK      32768    // 2^(3*MORT_BITS)
#define BCAP       128      // bucket capacity (Poisson mean 32; overflow prob ~e^-81)

#define SCAT_BLOCKS   4096                 // N_POINTS/256
#define REPACK_BLOCKS 32768                // TBL_TOTAL/256

// Static scratch (allocation-guard safe; zero-initialized at load):
__device__ float2 g_tbl[TBL_TOTAL];              // 64 MB feature-interleaved table
__device__ float4 g_slot[NBUCK * BCAP];          // 64 MB bucket slots (.w = orig idx)
__device__ int    g_cnt[NBUCK];                  // bucket counters (self-resetting)

struct ScalArr { float s[NUM_LEVELS]; };

__device__ __forceinline__ void repack_one(const float* __restrict__ ht, int i) {
    float a = __ldg(ht + i);
    float b = __ldg(ht + i + TBL_TOTAL);
    g_tbl[i] = make_float2(a, b);
}

// ---------------------------------------------------------------------------
// Morton bucket (5 bits/dim -> 15-bit code)
// ---------------------------------------------------------------------------
__device__ __forceinline__ unsigned mort5(unsigned v) {
    unsigned m = 0;
    #pragma unroll
    for (int b = 0; b < MORT_BITS; ++b) m |= ((v >> b) & 1u) << (3 * b);
    return m;
}

__device__ __forceinline__ unsigned bucket_of(float x, float y, float z) {
    unsigned ix = min(31u, (unsigned)(int)(x * 32.0f));
    unsigned iy = min(31u, (unsigned)(int)(y * 32.0f));
    unsigned iz = min(31u, (unsigned)(int)(z * 32.0f));
    return mort5(ix) | (mort5(iy) << 1) | (mort5(iz) << 2);
}

// ---------------------------------------------------------------------------
// Single aux kernel: bucket-scatter (atomic binning) + full table repack,
// co-scheduled on one grid.
// ---------------------------------------------------------------------------
__global__ __launch_bounds__(256) void combo_kernel(const float* __restrict__ x,
                                                    const float* __restrict__ ht) {
    int bid = blockIdx.x;
    if (bid < SCAT_BLOCKS) {
        int n = bid * 256 + threadIdx.x;
        float vx = x[3 * n + 0], vy = x[3 * n + 1], vz = x[3 * n + 2];
        unsigned b = bucket_of(vx, vy, vz);
        int pos = atomicAdd(&g_cnt[b], 1);
        pos = min(pos, BCAP - 1);   // safety clamp (statistically unreachable)
        g_slot[(size_t)b * BCAP + pos] = make_float4(vx, vy, vz, __int_as_float(n));
    } else {
        repack_one(ht, (bid - SCAT_BLOCKS) * 256 + threadIdx.x);
    }
}

// ---------------------------------------------------------------------------
// Scrambled weight: fracflat[k] = frac( coord[k%3] * scaling[k/3] )
// ---------------------------------------------------------------------------
__device__ __forceinline__ float fracw(float vx, float vy, float vz,
                                       const float* __restrict__ s, int k) {
    int d = k % 3;
    float v = (d == 0) ? vx : ((d == 1) ? vy : vz);
    float t = v * s[k / 3];
    return t - floorf(t);
}

// One level: gathers + scrambled trilinear blend -> 2 floats. Plain __ldg
// (L1+L2 allocate) — round 7 proved L2 residency is load-bearing.
__device__ __forceinline__ void enc_level(float vx, float vy, float vz,
                                          const ScalArr& sc, int L,
                                          float& out0, float& out1) {
    float s  = sc.s[L];
    float sx = vx * s, sy = vy * s, sz = vz * s;

    unsigned fx = (unsigned)(int)floorf(sx);
    unsigned cx = (unsigned)(int)ceilf(sx);
    unsigned fy = (unsigned)(int)floorf(sy);
    unsigned cy = (unsigned)(int)ceilf(sy);
    unsigned fz = (unsigned)(int)floorf(sz);
    unsigned cz = (unsigned)(int)ceilf(sz);

    unsigned hyf = fy * P2, hyc = cy * P2;
    unsigned hzf = fz * P3, hzc = cz * P3;

    const float2* __restrict__ tbl = g_tbl + (size_t)L * TABLE_SIZE;

    float2 F0 = __ldg(tbl + ((cx ^ hyc ^ hzc) & HMASK));
    float2 F1 = __ldg(tbl + ((cx ^ hyc ^ hzf) & HMASK));
    float2 F2 = __ldg(tbl + ((cx ^ hyf ^ hzc) & HMASK));
    float2 F3 = __ldg(tbl + ((fx ^ hyc ^ hzc) & HMASK));
    float2 F4 = __ldg(tbl + ((cx ^ hyf ^ hzf) & HMASK));
    float2 F5 = __ldg(tbl + ((fx ^ hyc ^ hzf) & HMASK));
    float2 F6 = __ldg(tbl + ((fx ^ hyf ^ hzc) & HMASK));
    float2 F7 = __ldg(tbl + ((fx ^ hyf ^ hzf) & HMASK));

    float wx = fracw(vx, vy, vz, sc.s, L);
    float wy = fracw(vx, vy, vz, sc.s, 16 + L);
    float wz = fracw(vx, vy, vz, sc.s, 32 + L);
    float qx = 1.0f - wx, qy = 1.0f - wy, qz = 1.0f - wz;

    {
        float f03 = F0.x * wx + F3.x * qx;
        float f12 = F1.x * wx + F2.x * qx;
        float f56 = F5.x * wx + F6.x * qx;
        float f47 = F4.x * wx + F7.x * qx;
        float a   = f03 * wy + f12 * qy;
        float b   = f47 * wy + f56 * qy;
        out0 = a * wz + b * qz;
    }
    {
        float f03 = F0.y * wx + F3.y * qx;
        float f12 = F1.y * wx + F2.y * qx;
        float f56 = F5.y * wx + F6.y * qx;
        float f47 = F4.y * wx + F7.y * qx;
        float a   = f03 * wy + f12 * qy;
        float b   = f47 * wy + f56 * qy;
        out1 = a * wz + b * qz;
    }
}

// ---------------------------------------------------------------------------
// Main encoding kernel: ONE WARP PER BUCKET. Warp reads its bucket count,
// resets it (for the next graph replay), and strides its points 32 at a time.
// Morton-adjacent buckets share a block for coarse-level L1 reuse.
// ---------------------------------------------------------------------------
__global__ __launch_bounds__(256, 5) void hashenc_kernel(
    float* __restrict__ out,
    ScalArr sc)
{
    int warp = (blockIdx.x * 256 + threadIdx.x) >> 5;   // bucket id
    int lane = threadIdx.x & 31;

    int c = min(g_cnt[warp], BCAP);    // broadcast read (same addr all lanes)
    __syncwarp();
    if (lane == 0) g_cnt[warp] = 0;    // reset for next replay

    const float4* slots = g_slot + (size_t)warp * BCAP;

    for (int i = lane; i < c; i += 32) {
        float4 p = slots[i];
        float vx = p.x, vy = p.y, vz = p.z;
        int orig = __float_as_int(p.w);

        float4* o = (float4*)(out + (size_t)orig * (2 * NUM_LEVELS));

        #pragma unroll
        for (int Lp = 0; Lp < NUM_LEVELS / 2; ++Lp) {
            float4 r;
            enc_level(vx, vy, vz, sc, 2 * Lp + 0, r.x, r.y);
            enc_level(vx, vy, vz, sc, 2 * Lp + 1, r.z, r.w);
            o[Lp] = r;
        }
    }
}

// ---------------------------------------------------------------------------
// Host: replicate numpy's SCALINGS bit-for-bit with double libm.
// ---------------------------------------------------------------------------
static void compute_scalings(ScalArr& a) {
    double growth = exp((log(2048.0) - log(16.0)) / 15.0);
    for (int l = 0; l < NUM_LEVELS; ++l)
        a.s[l] = (float)floor(16.0 * pow(growth, (double)l));
}

extern "C" void kernel_launch(void* const* d_in, const int* in_sizes, int n_in,
                              void* d_out, int out_size) {
    const float* x  = (const float*)d_in[0];
    const float* ht = (const float*)d_in[1];
    float* out = (float*)d_out;

    ScalArr sc;
    compute_scalings(sc);

    combo_kernel<<<SCAT_BLOCKS + REPACK_BLOCKS, 256>>>(x, ht);
    hashenc_kernel<<<NBUCK / 8, 256>>>(out, sc);   // 8 warps/block, 1 bucket/warp
}

// round 9
// speedup vs baseline: 1.3825x; 1.3404x over previous
#include <cuda_runtime.h>
#include <math.h>

#define TABLE_SIZE 524288
#define NUM_LEVELS 16
#define N_POINTS   1048576
#define TBL_TOTAL  (TABLE_SIZE * NUM_LEVELS)   // 8388608
#define HMASK      (TABLE_SIZE - 1)
#define P2         2654435761u
#define P3         805459861u

#define MORT_BITS  5
#define NBUCK      32768    // 2^(3*MORT_BITS)

#define HIST_BLOCKS   4096                 // N_POINTS/256
#define SCAT_BLOCKS   4096
#define R1_BLOCKS     20480                // repack share in K1
#define R2_BLOCKS     12288                // repack share in K2
#define R_OFF2        (R1_BLOCKS * 256)    // 5242880   (R1+R2 = 32768 blocks = TBL_TOTAL/256)

// Static scratch (allocation-guard safe; zero-initialized at load):
__device__ float2 g_tbl[TBL_TOTAL];      // 64 MB feature-interleaved table
__device__ float4 g_xs[N_POINTS];        // 16 MB sorted points (.w = orig idx)
__device__ int    g_hist[NBUCK];         // histogram (scan block resets it)
__device__ int    g_cursor[NBUCK];       // absolute exclusive scan -> running cursor
__device__ int    g_done;                // hist-block completion counter (self-resetting)

struct ScalArr { float s[NUM_LEVELS]; };

__device__ __forceinline__ void repack_one(const float* __restrict__ ht, int i) {
    float a = __ldg(ht + i);
    float b = __ldg(ht + i + TBL_TOTAL);
    g_tbl[i] = make_float2(a, b);
}

// ---------------------------------------------------------------------------
// Morton bucket (5 bits/dim -> 15-bit code)
// ---------------------------------------------------------------------------
__device__ __forceinline__ unsigned mort5(unsigned v) {
    unsigned m = 0;
    #pragma unroll
    for (int b = 0; b < MORT_BITS; ++b) m |= ((v >> b) & 1u) << (3 * b);
    return m;
}

__device__ __forceinline__ unsigned bucket_of(float x, float y, float z) {
    unsigned ix = min(31u, (unsigned)(int)(x * 32.0f));
    unsigned iy = min(31u, (unsigned)(int)(y * 32.0f));
    unsigned iz = min(31u, (unsigned)(int)(z * 32.0f));
    return mort5(ix) | (mort5(iy) << 1) | (mort5(iz) << 2);
}

// ---------------------------------------------------------------------------
// K1: histogram + inline last-block scan + repack part 1.
// The last hist block to finish scans all 32768 counts (exclusive, absolute),
// writes g_cursor, zeroes g_hist, resets g_done.
// ---------------------------------------------------------------------------
__global__ __launch_bounds__(256) void k1_kernel(const float* __restrict__ x,
                                                 const float* __restrict__ ht) {
    int bid = blockIdx.x;
    if (bid >= HIST_BLOCKS) {
        repack_one(ht, (bid - HIST_BLOCKS) * 256 + threadIdx.x);
        return;
    }

    int t = threadIdx.x;
    {
        int n = bid * 256 + t;
        float vx = x[3 * n + 0], vy = x[3 * n + 1], vz = x[3 * n + 2];
        atomicAdd(&g_hist[bucket_of(vx, vy, vz)], 1);
    }

    __shared__ int s_last;
    __shared__ int s_wsum[8];
    __threadfence();                 // make this thread's atomic globally ordered
    __syncthreads();
    if (t == 0) {
        int old = atomicAdd(&g_done, 1);
        s_last = (old == HIST_BLOCKS - 1);
    }
    __syncthreads();
    if (!s_last) return;

    // ---- inline scan: 256 threads x 128 buckets each ----
    const int PER = NBUCK / 256;     // 128
    int base = t * PER;

    // pass 1: per-thread total (L2 reads; skip possibly-stale L1)
    int tot = 0;
    for (int i = 0; i < PER; i += 4) {
        int4 v = __ldcg((const int4*)&g_hist[base + i]);
        tot += v.x + v.y + v.z + v.w;
    }

    // block exclusive scan of the 256 totals
    int lane = t & 31, w = t >> 5;
    int s = tot;
    #pragma unroll
    for (int off = 1; off < 32; off <<= 1) {
        int u = __shfl_up_sync(0xFFFFFFFF, s, off);
        if (lane >= off) s += u;
    }
    if (lane == 31) s_wsum[w] = s;
    __syncthreads();
    if (w == 0 && lane < 8) {
        int v8 = s_wsum[lane];
        int s8 = v8;
        #pragma unroll
        for (int off = 1; off < 8; off <<= 1) {
            int u = __shfl_up_sync(0xFF, s8, off);
            if (lane >= off) s8 += u;
        }
        s_wsum[lane] = s8 - v8;      // exclusive warp offsets
    }
    __syncthreads();
    int run = s_wsum[w] + (s - tot); // absolute exclusive prefix for this thread

    // pass 2: write absolute cursor, zero histogram
    const int4 z4 = make_int4(0, 0, 0, 0);
    for (int i = 0; i < PER; i += 4) {
        int4 v = __ldcg((const int4*)&g_hist[base + i]);
        int4 c;
        c.x = run; run += v.x;
        c.y = run; run += v.y;
        c.z = run; run += v.z;
        c.w = run; run += v.w;
        *(int4*)&g_cursor[base + i] = c;
        *(int4*)&g_hist[base + i]   = z4;   // reset for next replay
    }
    if (t == 0) g_done = 0;                 // reset for next replay
}

// ---------------------------------------------------------------------------
// K2: scatter (atomic cursor is already absolute) + repack part 2.
// ---------------------------------------------------------------------------
__global__ __launch_bounds__(256) void k2_kernel(const float* __restrict__ x,
                                                 const float* __restrict__ ht) {
    int bid = blockIdx.x;
    if (bid < SCAT_BLOCKS) {
        int n = bid * 256 + threadIdx.x;
        float vx = x[3 * n + 0], vy = x[3 * n + 1], vz = x[3 * n + 2];
        unsigned b = bucket_of(vx, vy, vz);
        int pos = atomicAdd(&g_cursor[b], 1);
        g_xs[pos] = make_float4(vx, vy, vz, __int_as_float(n));
    } else {
        repack_one(ht, R_OFF2 + (bid - SCAT_BLOCKS) * 256 + threadIdx.x);
    }
}

// ---------------------------------------------------------------------------
// Scrambled weight: fracflat[k] = frac( coord[k%3] * scaling[k/3] )
// ---------------------------------------------------------------------------
__device__ __forceinline__ float fracw(float vx, float vy, float vz,
                                       const float* __restrict__ s, int k) {
    int d = k % 3;
    float v = (d == 0) ? vx : ((d == 1) ? vy : vz);
    float t = v * s[k / 3];
    return t - floorf(t);
}

// One level: gathers + scrambled trilinear blend -> 2 floats. Plain __ldg —
// round 7 proved L2 residency is load-bearing; round 6 proved direct stores win.
__device__ __forceinline__ void enc_level(float vx, float vy, float vz,
                                          const ScalArr& sc, int L,
                                          float& out0, float& out1) {
    float s  = sc.s[L];
    float sx = vx * s, sy = vy * s, sz = vz * s;

    unsigned fx = (unsigned)(int)floorf(sx);
    unsigned cx = (unsigned)(int)ceilf(sx);
    unsigned fy = (unsigned)(int)floorf(sy);
    unsigned cy = (unsigned)(int)ceilf(sy);
    unsigned fz = (unsigned)(int)floorf(sz);
    unsigned cz = (unsigned)(int)ceilf(sz);

    unsigned hyf = fy * P2, hyc = cy * P2;
    unsigned hzf = fz * P3, hzc = cz * P3;

    const float2* __restrict__ tbl = g_tbl + (size_t)L * TABLE_SIZE;

    float2 F0 = __ldg(tbl + ((cx ^ hyc ^ hzc) & HMASK));
    float2 F1 = __ldg(tbl + ((cx ^ hyc ^ hzf) & HMASK));
    float2 F2 = __ldg(tbl + ((cx ^ hyf ^ hzc) & HMASK));
    float2 F3 = __ldg(tbl + ((fx ^ hyc ^ hzc) & HMASK));
    float2 F4 = __ldg(tbl + ((cx ^ hyf ^ hzf) & HMASK));
    float2 F5 = __ldg(tbl + ((fx ^ hyc ^ hzf) & HMASK));
    float2 F6 = __ldg(tbl + ((fx ^ hyf ^ hzc) & HMASK));
    float2 F7 = __ldg(tbl + ((fx ^ hyf ^ hzf) & HMASK));

    float wx = fracw(vx, vy, vz, sc.s, L);
    float wy = fracw(vx, vy, vz, sc.s, 16 + L);
    float wz = fracw(vx, vy, vz, sc.s, 32 + L);
    float qx = 1.0f - wx, qy = 1.0f - wy, qz = 1.0f - wz;

    {
        float f03 = F0.x * wx + F3.x * qx;
        float f12 = F1.x * wx + F2.x * qx;
        float f56 = F5.x * wx + F6.x * qx;
        float f47 = F4.x * wx + F7.x * qx;
        float a   = f03 * wy + f12 * qy;
        float b   = f47 * wy + f56 * qy;
        out0 = a * wz + b * qz;
    }
    {
        float f03 = F0.y * wx + F3.y * qx;
        float f12 = F1.y * wx + F2.y * qx;
        float f56 = F5.y * wx + F6.y * qx;
        float f47 = F4.y * wx + F7.y * qx;
        float a   = f03 * wy + f12 * qy;
        float b   = f47 * wy + f56 * qy;
        out1 = a * wz + b * qz;
    }
}

// ---------------------------------------------------------------------------
// Main encoding kernel: one thread per (Morton-sorted) point.
// Level pairs, direct float4 stores (proven 244-245 us configuration).
// ---------------------------------------------------------------------------
__global__ __launch_bounds__(256, 5) void hashenc_kernel(
    float* __restrict__ out,
    ScalArr sc)
{
    int n = blockIdx.x * blockDim.x + threadIdx.x;

    float4 p = g_xs[n];
    float vx = p.x, vy = p.y, vz = p.z;
    int orig = __float_as_int(p.w);

    float4* o = (float4*)(out + (size_t)orig * (2 * NUM_LEVELS));

    #pragma unroll
    for (int Lp = 0; Lp < NUM_LEVELS / 2; ++Lp) {
        float4 r;
        enc_level(vx, vy, vz, sc, 2 * Lp + 0, r.x, r.y);
        enc_level(vx, vy, vz, sc, 2 * Lp + 1, r.z, r.w);
        o[Lp] = r;
    }
}

// ---------------------------------------------------------------------------
// Host: replicate numpy's SCALINGS bit-for-bit with double libm.
// ---------------------------------------------------------------------------
static void compute_scalings(ScalArr& a) {
    double growth = exp((log(2048.0) - log(16.0)) / 15.0);
    for (int l = 0; l < NUM_LEVELS; ++l)
        a.s[l] = (float)floor(16.0 * pow(growth, (double)l));
}

extern "C" void kernel_launch(void* const* d_in, const int* in_sizes, int n_in,
                              void* d_out, int out_size) {
    const float* x  = (const float*)d_in[0];
    const float* ht = (const float*)d_in[1];
    float* out = (float*)d_out;

    ScalArr sc;
    compute_scalings(sc);

    k1_kernel<<<HIST_BLOCKS + R1_BLOCKS, 256>>>(x, ht);
    k2_kernel<<<SCAT_BLOCKS + R2_BLOCKS, 256>>>(x, ht);
    hashenc_kernel<<<N_POINTS / 256, 256>>>(out, sc);
}

// round 10
// speedup vs baseline: 1.4554x; 1.0528x over previous
#include <cuda_runtime.h>
#include <math.h>

#define TABLE_SIZE 524288
#define NUM_LEVELS 16
#define N_POINTS   1048576
#define TBL_TOTAL  (TABLE_SIZE * NUM_LEVELS)   // 8388608
#define HMASK      (TABLE_SIZE - 1)
#define P2         2654435761u
#define P3         805459861u

#define MORT_BITS  5
#define NBUCK      32768    // 2^(3*MORT_BITS)

#define AUX_BLOCKS 888      // 148 SMs x 6 — all co-resident (capacity 8/SM)
#define R_A        5242880  // repack elems in phase 1 (62.5%)
#define R_B        (TBL_TOTAL - R_A)

// Static scratch (allocation-guard safe; zero-initialized at load):
__device__ float2 g_tbl[TBL_TOTAL];      // 64 MB feature-interleaved table
__device__ float4 g_xs[N_POINTS];        // 16 MB sorted points (.w = orig idx)
__device__ int    g_hist[NBUCK];         // histogram (zeroed in phase 2)
__device__ int    g_cursor[NBUCK];       // chunk-relative exclusive scan -> cursor
__device__ int    g_bsum[32];            // per-chunk totals
__device__ int           g_barcnt;       // grid barrier (self-resetting)
__device__ volatile int  g_bargen;       // generation (monotonic across replays)

struct ScalArr { float s[NUM_LEVELS]; };

// ---------------------------------------------------------------------------
// Software grid barrier: all AUX_BLOCKS are co-resident by construction.
// One threadfence + one atomic per BLOCK.
// ---------------------------------------------------------------------------
__device__ __forceinline__ void grid_sync() {
    __syncthreads();
    if (threadIdx.x == 0) {
        __threadfence();
        int my = g_bargen;
        int old = atomicAdd(&g_barcnt, 1);
        if (old == AUX_BLOCKS - 1) {
            g_barcnt = 0;
            __threadfence();
            g_bargen = my + 1;
        } else {
            while (g_bargen == my) __nanosleep(64);
        }
    }
    __syncthreads();
}

__device__ __forceinline__ void repack_one(const float* __restrict__ ht, int i) {
    float a = __ldg(ht + i);
    float b = __ldg(ht + i + TBL_TOTAL);
    g_tbl[i] = make_float2(a, b);
}

// ---------------------------------------------------------------------------
// Morton bucket (5 bits/dim -> 15-bit code)
// ---------------------------------------------------------------------------
__device__ __forceinline__ unsigned mort5(unsigned v) {
    unsigned m = 0;
    #pragma unroll
    for (int b = 0; b < MORT_BITS; ++b) m |= ((v >> b) & 1u) << (3 * b);
    return m;
}

__device__ __forceinline__ unsigned bucket_of(float x, float y, float z) {
    unsigned ix = min(31u, (unsigned)(int)(x * 32.0f));
    unsigned iy = min(31u, (unsigned)(int)(y * 32.0f));
    unsigned iz = min(31u, (unsigned)(int)(z * 32.0f));
    return mort5(ix) | (mort5(iy) << 1) | (mort5(iz) << 2);
}

// ---------------------------------------------------------------------------
// Persistent aux kernel: hist -> scan -> scatter, repack overlapped in
// phases 1 and 2. Replaces three launches with one.
// ---------------------------------------------------------------------------
__global__ __launch_bounds__(256, 8) void aux_kernel(const float* __restrict__ x,
                                                     const float* __restrict__ ht) {
    const int t    = threadIdx.x;
    const int gtid = blockIdx.x * 256 + t;
    const int GT   = AUX_BLOCKS * 256;

    __shared__ int s_w[8];
    __shared__ int s_boff[32];

    // ---- Phase 1: histogram + repack part A ----
    for (int n = gtid; n < N_POINTS; n += GT) {
        float vx = x[3 * n + 0], vy = x[3 * n + 1], vz = x[3 * n + 2];
        atomicAdd(&g_hist[bucket_of(vx, vy, vz)], 1);
    }
    for (int i = gtid; i < R_A; i += GT) repack_one(ht, i);

    grid_sync();

    // ---- Phase 2: 32 blocks scan their 1024-bucket chunk; rest repack B ----
    if (blockIdx.x < 32) {
        int c = blockIdx.x;
        int base = c * 1024 + t * 4;
        int4 v = __ldcg((const int4*)&g_hist[base]);   // L2 read (atomics live in L2)
        int tot = v.x + v.y + v.z + v.w;

        // exclusive scan of 256 per-thread totals
        int lane = t & 31, w = t >> 5;
        int s = tot;
        #pragma unroll
        for (int off = 1; off < 32; off <<= 1) {
            int u = __shfl_up_sync(0xFFFFFFFF, s, off);
            if (lane >= off) s += u;
        }
        if (lane == 31) s_w[w] = s;
        __syncthreads();
        if (w == 0 && lane < 8) {
            int v8 = s_w[lane];
            int s8 = v8;
            #pragma unroll
            for (int off = 1; off < 8; off <<= 1) {
                int u = __shfl_up_sync(0xFF, s8, off);
                if (lane >= off) s8 += u;
            }
            s_w[lane] = s8 - v8;                       // exclusive warp offsets
        }
        __syncthreads();
        int run = s_w[w] + (s - tot);                  // chunk-relative exclusive

        int4 cu;
        cu.x = run; run += v.x;
        cu.y = run; run += v.y;
        cu.z = run; run += v.z;
        cu.w = run; run += v.w;
        *(int4*)&g_cursor[base] = cu;
        *(int4*)&g_hist[base]   = make_int4(0, 0, 0, 0);  // reset for next replay
        if (t == 255) g_bsum[c] = run;                 // chunk total
    } else {
        int gtid2 = (blockIdx.x - 32) * 256 + t;
        int GT2   = (AUX_BLOCKS - 32) * 256;
        for (int i = gtid2; i < R_B; i += GT2) repack_one(ht, R_A + i);
    }

    grid_sync();

    // ---- Phase 3: inline boff scan + scatter ----
    if (t < 32) {
        int v = __ldcg(&g_bsum[t]);
        int s = v;
        #pragma unroll
        for (int off = 1; off < 32; off <<= 1) {
            int u = __shfl_up_sync(0xFFFFFFFF, s, off);
            if (t >= off) s += u;
        }
        s_boff[t] = s - v;                             // exclusive chunk offsets
    }
    __syncthreads();

    for (int n = gtid; n < N_POINTS; n += GT) {
        float vx = x[3 * n + 0], vy = x[3 * n + 1], vz = x[3 * n + 2];
        unsigned b = bucket_of(vx, vy, vz);
        int pos = s_boff[b >> 10] + atomicAdd(&g_cursor[b], 1);
        g_xs[pos] = make_float4(vx, vy, vz, __int_as_float(n));
    }
}

// ---------------------------------------------------------------------------
// Scrambled weight: fracflat[k] = frac( coord[k%3] * scaling[k/3] )
// ---------------------------------------------------------------------------
__device__ __forceinline__ float fracw(float vx, float vy, float vz,
                                       const float* __restrict__ s, int k) {
    int d = k % 3;
    float v = (d == 0) ? vx : ((d == 1) ? vy : vz);
    float t = v * s[k / 3];
    return t - floorf(t);
}

// One level: gathers + scrambled trilinear blend -> 2 floats. Plain __ldg —
// L2 residency is load-bearing (R7); direct stores win (R6); dense
// thread-per-point execution is load-bearing (R8).
__device__ __forceinline__ void enc_level(float vx, float vy, float vz,
                                          const ScalArr& sc, int L,
                                          float& out0, float& out1) {
    float s  = sc.s[L];
    float sx = vx * s, sy = vy * s, sz = vz * s;

    unsigned fx = (unsigned)(int)floorf(sx);
    unsigned cx = (unsigned)(int)ceilf(sx);
    unsigned fy = (unsigned)(int)floorf(sy);
    unsigned cy = (unsigned)(int)ceilf(sy);
    unsigned fz = (unsigned)(int)floorf(sz);
    unsigned cz = (unsigned)(int)ceilf(sz);

    unsigned hyf = fy * P2, hyc = cy * P2;
    unsigned hzf = fz * P3, hzc = cz * P3;

    const float2* __restrict__ tbl = g_tbl + (size_t)L * TABLE_SIZE;

    float2 F0 = __ldg(tbl + ((cx ^ hyc ^ hzc) & HMASK));
    float2 F1 = __ldg(tbl + ((cx ^ hyc ^ hzf) & HMASK));
    float2 F2 = __ldg(tbl + ((cx ^ hyf ^ hzc) & HMASK));
    float2 F3 = __ldg(tbl + ((fx ^ hyc ^ hzc) & HMASK));
    float2 F4 = __ldg(tbl + ((cx ^ hyf ^ hzf) & HMASK));
    float2 F5 = __ldg(tbl + ((fx ^ hyc ^ hzf) & HMASK));
    float2 F6 = __ldg(tbl + ((fx ^ hyf ^ hzc) & HMASK));
    float2 F7 = __ldg(tbl + ((fx ^ hyf ^ hzf) & HMASK));

    float wx = fracw(vx, vy, vz, sc.s, L);
    float wy = fracw(vx, vy, vz, sc.s, 16 + L);
    float wz = fracw(vx, vy, vz, sc.s, 32 + L);
    float qx = 1.0f - wx, qy = 1.0f - wy, qz = 1.0f - wz;

    {
        float f03 = F0.x * wx + F3.x * qx;
        float f12 = F1.x * wx + F2.x * qx;
        float f56 = F5.x * wx + F6.x * qx;
        float f47 = F4.x * wx + F7.x * qx;
        float a   = f03 * wy + f12 * qy;
        float b   = f47 * wy + f56 * qy;
        out0 = a * wz + b * qz;
    }
    {
        float f03 = F0.y * wx + F3.y * qx;
        float f12 = F1.y * wx + F2.y * qx;
        float f56 = F5.y * wx + F6.y * qx;
        float f47 = F4.y * wx + F7.y * qx;
        float a   = f03 * wy + f12 * qy;
        float b   = f47 * wy + f56 * qy;
        out1 = a * wz + b * qz;
    }
}

// ---------------------------------------------------------------------------
// Main encoding kernel: one thread per (Morton-sorted) point.
// Level pairs, direct float4 stores (proven 244-245 us configuration).
// ---------------------------------------------------------------------------
__global__ __launch_bounds__(256, 5) void hashenc_kernel(
    float* __restrict__ out,
    ScalArr sc)
{
    int n = blockIdx.x * blockDim.x + threadIdx.x;

    float4 p = g_xs[n];
    float vx = p.x, vy = p.y, vz = p.z;
    int orig = __float_as_int(p.w);

    float4* o = (float4*)(out + (size_t)orig * (2 * NUM_LEVELS));

    #pragma unroll
    for (int Lp = 0; Lp < NUM_LEVELS / 2; ++Lp) {
        float4 r;
        enc_level(vx, vy, vz, sc, 2 * Lp + 0, r.x, r.y);
        enc_level(vx, vy, vz, sc, 2 * Lp + 1, r.z, r.w);
        o[Lp] = r;
    }
}

// ---------------------------------------------------------------------------
// Host: replicate numpy's SCALINGS bit-for-bit with double libm.
// ---------------------------------------------------------------------------
static void compute_scalings(ScalArr& a) {
    double growth = exp((log(2048.0) - log(16.0)) / 15.0);
    for (int l = 0; l < NUM_LEVELS; ++l)
        a.s[l] = (float)floor(16.0 * pow(growth, (double)l));
}

extern "C" void kernel_launch(void* const* d_in, const int* in_sizes, int n_in,
                              void* d_out, int out_size) {
    const float* x  = (const float*)d_in[0];
    const float* ht = (const float*)d_in[1];
    float* out = (float*)d_out;

    ScalArr sc;
    compute_scalings(sc);

    aux_kernel<<<AUX_BLOCKS, 256>>>(x, ht);
    hashenc_kernel<<<N_POINTS / 256, 256>>>(out, sc);
}

// round 11
// speedup vs baseline: 1.5719x; 1.0800x over previous
#include <cuda_runtime.h>
#include <math.h>

#define TABLE_SIZE 524288
#define NUM_LEVELS 16
#define N_POINTS   1048576
#define TBL_TOTAL  (TABLE_SIZE * NUM_LEVELS)   // 8388608
#define HMASK      (TABLE_SIZE - 1)
#define P2         2654435761u
#define P3         805459861u

#define MORT_BITS  5
#define NBUCK      32768    // 2^(3*MORT_BITS)

#define AUX_BLOCKS 888      // 148 SMs x 6 — all co-resident (capacity 8/SM)
#define R_A        5242880  // repack elems in phase 1 (62.5%)
#define R_B        (TBL_TOTAL - R_A)

// Static scratch (allocation-guard safe; zero-initialized at load):
__device__ float2 g_tbl[TBL_TOTAL];      // 64 MB feature-interleaved table
__device__ float4 g_xs[N_POINTS];        // 16 MB sorted points (.w = orig idx)
__device__ int    g_hist[NBUCK];         // histogram (zeroed in phase 2)
__device__ int    g_cursor[NBUCK];       // chunk-relative exclusive scan -> cursor
__device__ int    g_bsum[32];            // per-chunk totals
__device__ int           g_barcnt;       // grid barrier (self-resetting)
__device__ volatile int  g_bargen;       // generation (monotonic across replays)

struct ScalArr { float s[NUM_LEVELS]; };

// ---------------------------------------------------------------------------
// Software grid barrier: all AUX_BLOCKS are co-resident by construction.
// ---------------------------------------------------------------------------
__device__ __forceinline__ void grid_sync() {
    __syncthreads();
    if (threadIdx.x == 0) {
        __threadfence();
        int my = g_bargen;
        int old = atomicAdd(&g_barcnt, 1);
        if (old == AUX_BLOCKS - 1) {
            g_barcnt = 0;
            __threadfence();
            g_bargen = my + 1;
        } else {
            while (g_bargen == my) __nanosleep(64);
        }
    }
    __syncthreads();
}

__device__ __forceinline__ void repack_one(const float* __restrict__ ht, int i) {
    float a = __ldg(ht + i);
    float b = __ldg(ht + i + TBL_TOTAL);
    g_tbl[i] = make_float2(a, b);
}

// ---------------------------------------------------------------------------
// Morton bucket (5 bits/dim -> 15-bit code)
// ---------------------------------------------------------------------------
__device__ __forceinline__ unsigned mort5(unsigned v) {
    unsigned m = 0;
    #pragma unroll
    for (int b = 0; b < MORT_BITS; ++b) m |= ((v >> b) & 1u) << (3 * b);
    return m;
}

__device__ __forceinline__ unsigned bucket_of(float x, float y, float z) {
    unsigned ix = min(31u, (unsigned)(int)(x * 32.0f));
    unsigned iy = min(31u, (unsigned)(int)(y * 32.0f));
    unsigned iz = min(31u, (unsigned)(int)(z * 32.0f));
    return mort5(ix) | (mort5(iy) << 1) | (mort5(iz) << 2);
}

// ---------------------------------------------------------------------------
// Persistent aux kernel: hist -> scan -> scatter, repack overlapped.
// ---------------------------------------------------------------------------
__global__ __launch_bounds__(256, 8) void aux_kernel(const float* __restrict__ x,
                                                     const float* __restrict__ ht) {
    const int t    = threadIdx.x;
    const int gtid = blockIdx.x * 256 + t;
    const int GT   = AUX_BLOCKS * 256;

    __shared__ int s_w[8];
    __shared__ int s_boff[32];

    // ---- Phase 1: histogram + repack part A ----
    for (int n = gtid; n < N_POINTS; n += GT) {
        float vx = x[3 * n + 0], vy = x[3 * n + 1], vz = x[3 * n + 2];
        atomicAdd(&g_hist[bucket_of(vx, vy, vz)], 1);
    }
    for (int i = gtid; i < R_A; i += GT) repack_one(ht, i);

    grid_sync();

    // ---- Phase 2: 32 blocks scan their 1024-bucket chunk; rest repack B ----
    if (blockIdx.x < 32) {
        int c = blockIdx.x;
        int base = c * 1024 + t * 4;
        int4 v = __ldcg((const int4*)&g_hist[base]);
        int tot = v.x + v.y + v.z + v.w;

        int lane = t & 31, w = t >> 5;
        int s = tot;
        #pragma unroll
        for (int off = 1; off < 32; off <<= 1) {
            int u = __shfl_up_sync(0xFFFFFFFF, s, off);
            if (lane >= off) s += u;
        }
        if (lane == 31) s_w[w] = s;
        __syncthreads();
        if (w == 0 && lane < 8) {
            int v8 = s_w[lane];
            int s8 = v8;
            #pragma unroll
            for (int off = 1; off < 8; off <<= 1) {
                int u = __shfl_up_sync(0xFF, s8, off);
                if (lane >= off) s8 += u;
            }
            s_w[lane] = s8 - v8;
        }
        __syncthreads();
        int run = s_w[w] + (s - tot);

        int4 cu;
        cu.x = run; run += v.x;
        cu.y = run; run += v.y;
        cu.z = run; run += v.z;
        cu.w = run; run += v.w;
        *(int4*)&g_cursor[base] = cu;
        *(int4*)&g_hist[base]   = make_int4(0, 0, 0, 0);
        if (t == 255) g_bsum[c] = run;
    } else {
        int gtid2 = (blockIdx.x - 32) * 256 + t;
        int GT2   = (AUX_BLOCKS - 32) * 256;
        for (int i = gtid2; i < R_B; i += GT2) repack_one(ht, R_A + i);
    }

    grid_sync();

    // ---- Phase 3: inline boff scan + scatter ----
    if (t < 32) {
        int v = __ldcg(&g_bsum[t]);
        int s = v;
        #pragma unroll
        for (int off = 1; off < 32; off <<= 1) {
            int u = __shfl_up_sync(0xFFFFFFFF, s, off);
            if (t >= off) s += u;
        }
        s_boff[t] = s - v;
    }
    __syncthreads();

    for (int n = gtid; n < N_POINTS; n += GT) {
        float vx = x[3 * n + 0], vy = x[3 * n + 1], vz = x[3 * n + 2];
        unsigned b = bucket_of(vx, vy, vz);
        int pos = s_boff[b >> 10] + atomicAdd(&g_cursor[b], 1);
        g_xs[pos] = make_float4(vx, vy, vz, __int_as_float(n));
    }
}

// ---------------------------------------------------------------------------
// Scrambled weight: fracflat[k] = frac( coord[k%3] * scaling[k/3] )
// ---------------------------------------------------------------------------
__device__ __forceinline__ float fracw(float vx, float vy, float vz,
                                       const float* __restrict__ s, int k) {
    int d = k % 3;
    float v = (d == 0) ? vx : ((d == 1) ? vy : vz);
    float t = v * s[k / 3];
    return t - floorf(t);
}

// ---------------------------------------------------------------------------
// Paired x-corner gather. PRIMES[0]==1, so the two x-corners of a cell hash
// to i0 = fx^m and i1 = (fx+1)^m. When fx is even these are the two halves
// of ONE 16B-aligned float4 -> one load, one sector, one wavefront.
// The (i0^i1)<=1 test also covers the cx==fx exact-integer edge case.
// ---------------------------------------------------------------------------
__device__ __forceinline__ void ld_xpair(const float2* __restrict__ tbl,
                                         unsigned fx, unsigned cx, unsigned m,
                                         float2& Ff, float2& Fc) {
    unsigned i0 = (fx ^ m) & HMASK;
    unsigned i1 = (cx ^ m) & HMASK;
    float4 q = __ldg((const float4*)(tbl + (i0 & ~1u)));
    float2 lo = make_float2(q.x, q.y);
    float2 hi = make_float2(q.z, q.w);
    Ff = (i0 & 1u) ? hi : lo;
    if ((i0 ^ i1) <= 1u) {
        Fc = (i1 & 1u) ? hi : lo;          // same aligned pair: free
    } else {
        Fc = __ldg(tbl + i1);              // predicated second load (~50% lanes)
    }
}

// One level: 4 paired gathers + scrambled trilinear blend -> 2 floats.
__device__ __forceinline__ void enc_level(float vx, float vy, float vz,
                                          const ScalArr& sc, int L,
                                          float& out0, float& out1) {
    float s  = sc.s[L];
    float sx = vx * s, sy = vy * s, sz = vz * s;

    unsigned fx = (unsigned)(int)floorf(sx);
    unsigned cx = (unsigned)(int)ceilf(sx);
    unsigned fy = (unsigned)(int)floorf(sy);
    unsigned cy = (unsigned)(int)ceilf(sy);
    unsigned fz = (unsigned)(int)floorf(sz);
    unsigned cz = (unsigned)(int)ceilf(sz);

    unsigned hyf = fy * P2, hyc = cy * P2;
    unsigned hzf = fz * P3, hzc = cz * P3;

    const float2* __restrict__ tbl = g_tbl + (size_t)L * TABLE_SIZE;

    // x-pairs (Ff = floor-x corner, Fc = ceil-x corner):
    float2 F0, F1, F2, F3, F4, F5, F6, F7;
    ld_xpair(tbl, fx, cx, hyc ^ hzc, F3, F0);
    ld_xpair(tbl, fx, cx, hyc ^ hzf, F5, F1);
    ld_xpair(tbl, fx, cx, hyf ^ hzc, F6, F2);
    ld_xpair(tbl, fx, cx, hyf ^ hzf, F7, F4);

    float wx = fracw(vx, vy, vz, sc.s, L);
    float wy = fracw(vx, vy, vz, sc.s, 16 + L);
    float wz = fracw(vx, vy, vz, sc.s, 32 + L);
    float qx = 1.0f - wx, qy = 1.0f - wy, qz = 1.0f - wz;

    {
        float f03 = F0.x * wx + F3.x * qx;
        float f12 = F1.x * wx + F2.x * qx;
        float f56 = F5.x * wx + F6.x * qx;
        float f47 = F4.x * wx + F7.x * qx;
        float a   = f03 * wy + f12 * qy;
        float b   = f47 * wy + f56 * qy;
        out0 = a * wz + b * qz;
    }
    {
        float f03 = F0.y * wx + F3.y * qx;
        float f12 = F1.y * wx + F2.y * qx;
        float f56 = F5.y * wx + F6.y * qx;
        float f47 = F4.y * wx + F7.y * qx;
        float a   = f03 * wy + f12 * qy;
        float b   = f47 * wy + f56 * qy;
        out1 = a * wz + b * qz;
    }
}

// ---------------------------------------------------------------------------
// Main encoding kernel: one thread per (Morton-sorted) point.
// ---------------------------------------------------------------------------
__global__ __launch_bounds__(256, 4) void hashenc_kernel(
    float* __restrict__ out,
    ScalArr sc)
{
    int n = blockIdx.x * blockDim.x + threadIdx.x;

    float4 p = g_xs[n];
    float vx = p.x, vy = p.y, vz = p.z;
    int orig = __float_as_int(p.w);

    float4* o = (float4*)(out + (size_t)orig * (2 * NUM_LEVELS));

    #pragma unroll
    for (int Lp = 0; Lp < NUM_LEVELS / 2; ++Lp) {
        float4 r;
        enc_level(vx, vy, vz, sc, 2 * Lp + 0, r.x, r.y);
        enc_level(vx, vy, vz, sc, 2 * Lp + 1, r.z, r.w);
        o[Lp] = r;
    }
}

// ---------------------------------------------------------------------------
// Host: replicate numpy's SCALINGS bit-for-bit with double libm.
// ---------------------------------------------------------------------------
static void compute_scalings(ScalArr& a) {
    double growth = exp((log(2048.0) - log(16.0)) / 15.0);
    for (int l = 0; l < NUM_LEVELS; ++l)
        a.s[l] = (float)floor(16.0 * pow(growth, (double)l));
}

extern "C" void kernel_launch(void* const* d_in, const int* in_sizes, int n_in,
                              void* d_out, int out_size) {
    const float* x  = (const float*)d_in[0];
    const float* ht = (const float*)d_in[1];
    float* out = (float*)d_out;

    ScalArr sc;
    compute_scalings(sc);

    aux_kernel<<<AUX_BLOCKS, 256>>>(x, ht);
    hashenc_kernel<<<N_POINTS / 256, 256>>>(out, sc);
}